// round 1
// baseline (speedup 1.0000x reference)
#include <cuda_runtime.h>
#include <math.h>

// Problem constants
static const int BATCH  = 4;
static const int SEQ    = 2048;
static const int DIM    = 1024;
static const int NHEAD  = 16;
static const int HDIM   = 64;
static const int LATENT = 128;
static const int QRANK  = 256;
static const int MTOT   = BATCH * SEQ;          // 8192
static const int KVLD   = 2 * DIM;              // 2048 (K|V concat row)

// Scratch (no allocations allowed) ------------------------------------------
__device__ float g_kvlat[(size_t)MTOT * LATENT];        //  4 MB
__device__ float g_kvup [(size_t)MTOT * 2 * DIM];       // 64 MB  (K | V)
__device__ float g_qlat [(size_t)MTOT * QRANK];         //  8 MB
__device__ float g_q    [(size_t)MTOT * DIM];           // 32 MB
__device__ float g_ctx  [(size_t)MTOT * DIM];           // 32 MB

// ---------------------------------------------------------------------------
// Generic fp32 GEMM: C[M,N] = A[M,K] @ W[K,N] + bias[N]
// 64x64 tile, BK=16, 256 threads, 4x4 per-thread micro-tile.
// Requires M%64==0, N%64==0, K%16==0 (true for all 5 calls).
// ---------------------------------------------------------------------------
__global__ __launch_bounds__(256) void gemm_bias_kernel(
    const float* __restrict__ A, const float* __restrict__ W,
    const float* __restrict__ bias, float* __restrict__ C,
    int M, int N, int K)
{
    __shared__ float As[16][64];   // transposed: As[k][m]
    __shared__ float Bs[16][64];   // Bs[k][n]

    const int tid = threadIdx.x;
    const int bn  = blockIdx.x * 64;
    const int bm  = blockIdx.y * 64;

    const int m0 = (tid >> 4) << 2;      // 0..60
    const int n0 = (tid & 15) << 2;      // 0..60

    // A loader: each thread one float4 along K
    const int a_m = tid >> 2;            // 0..63
    const int a_k = (tid & 3) << 2;      // 0,4,8,12
    // B loader: each thread one float4 along N
    const int b_k = tid >> 4;            // 0..15
    const int b_n = (tid & 15) << 2;     // 0..60

    const float* Aptr = A + (size_t)(bm + a_m) * K + a_k;
    const float* Wptr = W + (size_t)b_k * N + bn + b_n;

    float acc[4][4] = {};

    for (int k0 = 0; k0 < K; k0 += 16) {
        float4 av = *(const float4*)(Aptr + k0);
        As[a_k + 0][a_m] = av.x;
        As[a_k + 1][a_m] = av.y;
        As[a_k + 2][a_m] = av.z;
        As[a_k + 3][a_m] = av.w;
        *(float4*)&Bs[b_k][b_n] = *(const float4*)(Wptr + (size_t)k0 * N);
        __syncthreads();

#pragma unroll
        for (int kk = 0; kk < 16; kk++) {
            float a0 = As[kk][m0 + 0];
            float a1 = As[kk][m0 + 1];
            float a2 = As[kk][m0 + 2];
            float a3 = As[kk][m0 + 3];
            float4 bv = *(float4*)&Bs[kk][n0];
            acc[0][0] += a0 * bv.x; acc[0][1] += a0 * bv.y; acc[0][2] += a0 * bv.z; acc[0][3] += a0 * bv.w;
            acc[1][0] += a1 * bv.x; acc[1][1] += a1 * bv.y; acc[1][2] += a1 * bv.z; acc[1][3] += a1 * bv.w;
            acc[2][0] += a2 * bv.x; acc[2][1] += a2 * bv.y; acc[2][2] += a2 * bv.z; acc[2][3] += a2 * bv.w;
            acc[3][0] += a3 * bv.x; acc[3][1] += a3 * bv.y; acc[3][2] += a3 * bv.z; acc[3][3] += a3 * bv.w;
        }
        __syncthreads();
    }

    float4 bb = *(const float4*)(bias + bn + n0);
#pragma unroll
    for (int i = 0; i < 4; i++) {
        float4 o;
        o.x = acc[i][0] + bb.x;
        o.y = acc[i][1] + bb.y;
        o.z = acc[i][2] + bb.z;
        o.w = acc[i][3] + bb.w;
        *(float4*)(C + (size_t)(bm + m0 + i) * N + bn + n0) = o;
    }
}

// ---------------------------------------------------------------------------
// Flash attention (causal), hd=64, 64x64 tiles, 256 threads per block.
// grid = (SEQ/64, BATCH*NHEAD). Q: [B,S,DIM] (head h at col h*64),
// KV: [B,S,2*DIM] (K at col h*64, V at col DIM + h*64), ctx: [B,S,DIM].
// ---------------------------------------------------------------------------
static const int PAD = 68;  // 64 + 4: kills stride-64 bank conflicts

__global__ __launch_bounds__(256) void attn_kernel(
    const float* __restrict__ Q, const float* __restrict__ KV,
    float* __restrict__ ctx)
{
    extern __shared__ float sm[];
    float* sQ = sm;                 // [64][PAD]
    float* sK = sm + 64 * PAD;      // [64][PAD]
    float* sV = sm + 2 * 64 * PAD;  // [64][PAD]
    float* sP = sm + 3 * 64 * PAD;  // [64][PAD]

    const int qb  = blockIdx.x;
    const int b   = blockIdx.y >> 4;
    const int h   = blockIdx.y & 15;
    const int tid = threadIdx.x;
    const int r0  = (tid >> 4) << 2;   // query rows owned (4)
    const int c0  = (tid & 15) << 2;   // key cols / out dims owned (4)

    const float* Qb = Q  + ((size_t)b * SEQ + (size_t)qb * 64) * DIM + h * HDIM;
    const float* Kb = KV + (size_t)b * SEQ * KVLD + h * HDIM;
    const float* Vb = Kb + DIM;

    // load Q tile (each thread 4 float4s)
#pragma unroll
    for (int i = 0; i < 4; i++) {
        int idx = tid + (i << 8);            // float4 index 0..1023
        int r = idx >> 4, c = (idx & 15) << 2;
        *(float4*)&sQ[r * PAD + c] = *(const float4*)(Qb + (size_t)r * DIM + c);
    }

    float mrow[4], lrow[4], O[4][4];
#pragma unroll
    for (int i = 0; i < 4; i++) {
        mrow[i] = -INFINITY; lrow[i] = 0.f;
        O[i][0] = O[i][1] = O[i][2] = O[i][3] = 0.f;
    }

    for (int j = 0; j <= qb; j++) {
        __syncthreads();   // previous PV read of sV / sP done
#pragma unroll
        for (int i = 0; i < 4; i++) {
            int idx = tid + (i << 8);
            int r = idx >> 4, c = (idx & 15) << 2;
            const float* kp = Kb + (size_t)(j * 64 + r) * KVLD + c;
            *(float4*)&sK[r * PAD + c] = *(const float4*)kp;
            *(float4*)&sV[r * PAD + c] = *(const float4*)(kp + DIM);
        }
        __syncthreads();

        // S = Q @ K^T  (this thread: rows r0..r0+3, cols c0..c0+3)
        float s[4][4] = {};
        for (int d = 0; d < 64; d += 4) {
            float4 qv[4], kv[4];
#pragma unroll
            for (int i = 0; i < 4; i++) {
                qv[i] = *(float4*)&sQ[(r0 + i) * PAD + d];
                kv[i] = *(float4*)&sK[(c0 + i) * PAD + d];
            }
#pragma unroll
            for (int i = 0; i < 4; i++)
#pragma unroll
                for (int jj = 0; jj < 4; jj++) {
                    s[i][jj] += qv[i].x * kv[jj].x + qv[i].y * kv[jj].y
                              + qv[i].z * kv[jj].z + qv[i].w * kv[jj].w;
                }
        }

        const float sc = 0.125f;  // 1/sqrt(64)
        if (j == qb) {
#pragma unroll
            for (int i = 0; i < 4; i++)
#pragma unroll
                for (int jj = 0; jj < 4; jj++)
                    s[i][jj] = (c0 + jj <= r0 + i) ? s[i][jj] * sc : -1e30f;
        } else {
#pragma unroll
            for (int i = 0; i < 4; i++)
#pragma unroll
                for (int jj = 0; jj < 4; jj++)
                    s[i][jj] *= sc;
        }

        // online softmax + write P
#pragma unroll
        for (int i = 0; i < 4; i++) {
            float mx = fmaxf(fmaxf(s[i][0], s[i][1]), fmaxf(s[i][2], s[i][3]));
            mx = fmaxf(mx, __shfl_xor_sync(0xffffffffu, mx, 1));
            mx = fmaxf(mx, __shfl_xor_sync(0xffffffffu, mx, 2));
            mx = fmaxf(mx, __shfl_xor_sync(0xffffffffu, mx, 4));
            mx = fmaxf(mx, __shfl_xor_sync(0xffffffffu, mx, 8));
            float mnew  = fmaxf(mrow[i], mx);
            float alpha = __expf(mrow[i] - mnew);
            mrow[i] = mnew;
            float4 p;
            p.x = __expf(s[i][0] - mnew);
            p.y = __expf(s[i][1] - mnew);
            p.z = __expf(s[i][2] - mnew);
            p.w = __expf(s[i][3] - mnew);
            float rs = p.x + p.y + p.z + p.w;
            rs += __shfl_xor_sync(0xffffffffu, rs, 1);
            rs += __shfl_xor_sync(0xffffffffu, rs, 2);
            rs += __shfl_xor_sync(0xffffffffu, rs, 4);
            rs += __shfl_xor_sync(0xffffffffu, rs, 8);
            lrow[i] = lrow[i] * alpha + rs;
            O[i][0] *= alpha; O[i][1] *= alpha; O[i][2] *= alpha; O[i][3] *= alpha;
            *(float4*)&sP[(r0 + i) * PAD + c0] = p;
        }
        __syncthreads();

        // O += P @ V  (this thread: rows r0.., dims c0..)
        for (int k = 0; k < 64; k++) {
            float4 vv = *(float4*)&sV[k * PAD + c0];
            float p0 = sP[(r0 + 0) * PAD + k];
            float p1 = sP[(r0 + 1) * PAD + k];
            float p2 = sP[(r0 + 2) * PAD + k];
            float p3 = sP[(r0 + 3) * PAD + k];
            O[0][0] += p0 * vv.x; O[0][1] += p0 * vv.y; O[0][2] += p0 * vv.z; O[0][3] += p0 * vv.w;
            O[1][0] += p1 * vv.x; O[1][1] += p1 * vv.y; O[1][2] += p1 * vv.z; O[1][3] += p1 * vv.w;
            O[2][0] += p2 * vv.x; O[2][1] += p2 * vv.y; O[2][2] += p2 * vv.z; O[2][3] += p2 * vv.w;
            O[3][0] += p3 * vv.x; O[3][1] += p3 * vv.y; O[3][2] += p3 * vv.z; O[3][3] += p3 * vv.w;
        }
    }

    // epilogue: normalize, write ctx
#pragma unroll
    for (int i = 0; i < 4; i++) {
        float inv = 1.0f / lrow[i];
        float4 o;
        o.x = O[i][0] * inv; o.y = O[i][1] * inv;
        o.z = O[i][2] * inv; o.w = O[i][3] * inv;
        *(float4*)(ctx + ((size_t)b * SEQ + (size_t)qb * 64 + r0 + i) * DIM + h * HDIM + c0) = o;
    }
}

// ---------------------------------------------------------------------------
extern "C" void kernel_launch(void* const* d_in, const int* in_sizes, int n_in,
                              void* d_out, int out_size)
{
    const float* x      = (const float*)d_in[0];
    // d_in[1] = mask (int32 tril) — causality handled analytically, unused
    const float* w_kvc  = (const float*)d_in[2];
    const float* b_kvc  = (const float*)d_in[3];
    const float* w_kvu  = (const float*)d_in[4];
    const float* b_kvu  = (const float*)d_in[5];
    const float* w_qc   = (const float*)d_in[6];
    const float* b_qc   = (const float*)d_in[7];
    const float* w_qu   = (const float*)d_in[8];
    const float* b_qu   = (const float*)d_in[9];
    const float* w_o    = (const float*)d_in[10];
    const float* b_o    = (const float*)d_in[11];
    float* out = (float*)d_out;

    float *kvlat, *kvup, *qlat, *q, *ctx;
    cudaGetSymbolAddress((void**)&kvlat, g_kvlat);
    cudaGetSymbolAddress((void**)&kvup,  g_kvup);
    cudaGetSymbolAddress((void**)&qlat,  g_qlat);
    cudaGetSymbolAddress((void**)&q,     g_q);
    cudaGetSymbolAddress((void**)&ctx,   g_ctx);

    dim3 t(256);

    // kv_latent = x @ w_kvc + b_kvc              [8192,128]
    gemm_bias_kernel<<<dim3(LATENT / 64, MTOT / 64), t>>>(x, w_kvc, b_kvc, kvlat, MTOT, LATENT, DIM);
    // kv_up = kv_latent @ w_kvu + b_kvu          [8192,2048] = K|V
    gemm_bias_kernel<<<dim3(2 * DIM / 64, MTOT / 64), t>>>(kvlat, w_kvu, b_kvu, kvup, MTOT, 2 * DIM, LATENT);
    // q_latent = x @ w_qc + b_qc                 [8192,256]
    gemm_bias_kernel<<<dim3(QRANK / 64, MTOT / 64), t>>>(x, w_qc, b_qc, qlat, MTOT, QRANK, DIM);
    // Q = q_latent @ w_qu + b_qu                 [8192,1024]
    gemm_bias_kernel<<<dim3(DIM / 64, MTOT / 64), t>>>(qlat, w_qu, b_qu, q, MTOT, DIM, QRANK);

    // attention -> ctx
    const int smem_bytes = 4 * 64 * PAD * (int)sizeof(float);  // 69632
    cudaFuncSetAttribute(attn_kernel, cudaFuncAttributeMaxDynamicSharedMemorySize, smem_bytes);
    attn_kernel<<<dim3(SEQ / 64, BATCH * NHEAD), t, smem_bytes>>>(q, kvup, ctx);

    // out = ctx @ w_o + b_o                      [8192,1024]
    gemm_bias_kernel<<<dim3(DIM / 64, MTOT / 64), t>>>(ctx, w_o, b_o, out, MTOT, DIM, DIM);
}

// round 4
// speedup vs baseline: 6.0732x; 6.0732x over previous
#include <cuda_runtime.h>
#include <math.h>

// Problem constants
static const int BATCH  = 4;
static const int SEQ    = 2048;
static const int DIM    = 1024;
static const int NHEAD  = 16;
static const int HDIM   = 64;
static const int LATENT = 128;
static const int QRANK  = 256;
static const int MTOT   = BATCH * SEQ;          // 8192
static const int KVLD   = 2 * DIM;              // 2048

// Scratch (no allocations allowed) ------------------------------------------
__device__ float g_kvlat[(size_t)MTOT * LATENT];
__device__ float g_kvup [(size_t)MTOT * 2 * DIM];
__device__ float g_qlat [(size_t)MTOT * QRANK];
__device__ float g_q    [(size_t)MTOT * DIM];
__device__ float g_ctx  [(size_t)MTOT * DIM];

// ---------------------------------------------------------------------------
// tf32 helpers
// ---------------------------------------------------------------------------
__device__ __forceinline__ unsigned f2tf(float x) {
    unsigned u;
    asm("cvt.rna.tf32.f32 %0, %1;" : "=r"(u) : "f"(x));
    return u;
}

__device__ __forceinline__ void mma_tf32(float* d, const unsigned* a, const unsigned* b) {
    asm volatile(
        "mma.sync.aligned.m16n8k8.row.col.f32.tf32.tf32.f32 "
        "{%0,%1,%2,%3}, {%4,%5,%6,%7}, {%8,%9}, {%0,%1,%2,%3};"
        : "+f"(d[0]), "+f"(d[1]), "+f"(d[2]), "+f"(d[3])
        : "r"(a[0]), "r"(a[1]), "r"(a[2]), "r"(a[3]), "r"(b[0]), "r"(b[1]));
}

__device__ __forceinline__ void cpa16(float* smem, const float* g) {
    unsigned s = (unsigned)__cvta_generic_to_shared(smem);
    asm volatile("cp.async.cg.shared.global [%0], [%1], 16;" :: "r"(s), "l"(g));
}
__device__ __forceinline__ void cp_commit() { asm volatile("cp.async.commit_group;"); }
__device__ __forceinline__ void cp_wait1()  { asm volatile("cp.async.wait_group 1;"); }
__device__ __forceinline__ void cp_wait0()  { asm volatile("cp.async.wait_group 0;"); }

// ---------------------------------------------------------------------------
// tf32 GEMM: C[M,N] = A[M,K] @ W[K,N] + bias. BM=BN=128, BK=32, 256 threads.
// Requires M%128==0, N%128==0, K%32==0.
// smem: A tiles [2][128][36], W tiles [2][32][136]  (pads -> conflict-free frags)
// ---------------------------------------------------------------------------
static const int GA_STRIDE = 128 * 36;  // floats per A buffer
static const int GW_STRIDE = 32 * 136;  // floats per W buffer
static const int GEMM_SMEM = (2 * GA_STRIDE + 2 * GW_STRIDE) * 4;  // 71680 B

__global__ __launch_bounds__(256, 2) void gemm_tf32_kernel(
    const float* __restrict__ A, const float* __restrict__ W,
    const float* __restrict__ bias, float* __restrict__ C,
    int M, int N, int K)
{
    extern __shared__ float sm[];
    float* sA = sm;                   // [2][128][36]
    float* sW = sm + 2 * GA_STRIDE;   // [2][32][136]

    const int tid  = threadIdx.x;
    const int lane = tid & 31;
    const int warp = tid >> 5;
    const int gid  = lane >> 2;   // groupID
    const int tig  = lane & 3;    // thread in group
    const int bm   = blockIdx.y * 128;
    const int bn   = blockIdx.x * 128;
    const int wm   = (warp & 3) * 32;
    const int wn   = (warp >> 2) * 64;

    // loader coords
    const int a_r = tid >> 3;           // 0..31 (+32 per i)
    const int a_c = (tid & 7) * 4;      // 0..28
    const int w_r = tid >> 5;           // 0..7 (+8 per i)
    const int w_c = (tid & 31) * 4;     // 0..124

    const float* Ag = A + (size_t)(bm + a_r) * K + a_c;
    const float* Wg = W + (size_t)w_r * N + bn + w_c;

    float acc[2][8][4] = {};

    const int NC = K / 32;

    // prologue: load chunk 0 into buf 0
    {
        float* dA = sA;
        float* dW = sW;
#pragma unroll
        for (int i = 0; i < 4; i++)
            cpa16(dA + (a_r + i * 32) * 36 + a_c, Ag + (size_t)i * 32 * K);
#pragma unroll
        for (int i = 0; i < 4; i++)
            cpa16(dW + (w_r + i * 8) * 136 + w_c, Wg + (size_t)i * 8 * N);
        cp_commit();
    }

    for (int c = 0; c < NC; ++c) {
        const int buf = c & 1;
        if (c + 1 < NC) {
            float* dA = sA + (buf ^ 1) * GA_STRIDE;
            float* dW = sW + (buf ^ 1) * GW_STRIDE;
            const float* Agc = Ag + (c + 1) * 32;
            const float* Wgc = Wg + (size_t)(c + 1) * 32 * N;
#pragma unroll
            for (int i = 0; i < 4; i++)
                cpa16(dA + (a_r + i * 32) * 36 + a_c, Agc + (size_t)i * 32 * K);
#pragma unroll
            for (int i = 0; i < 4; i++)
                cpa16(dW + (w_r + i * 8) * 136 + w_c, Wgc + (size_t)i * 8 * N);
            cp_commit();
            cp_wait1();
        } else {
            cp_wait0();
        }
        __syncthreads();

        const float* ab = sA + buf * GA_STRIDE;
        const float* wb = sW + buf * GW_STRIDE;
#pragma unroll
        for (int ks = 0; ks < 4; ks++) {
            unsigned af[2][4];
#pragma unroll
            for (int mt = 0; mt < 2; mt++) {
                const float* p = ab + (wm + mt * 16 + gid) * 36 + ks * 8 + tig;
                af[mt][0] = f2tf(p[0]);
                af[mt][1] = f2tf(p[8 * 36]);
                af[mt][2] = f2tf(p[4]);
                af[mt][3] = f2tf(p[8 * 36 + 4]);
            }
            unsigned bf[8][2];
#pragma unroll
            for (int nt = 0; nt < 8; nt++) {
                const float* p = wb + (ks * 8 + tig) * 136 + wn + nt * 8 + gid;
                bf[nt][0] = f2tf(p[0]);
                bf[nt][1] = f2tf(p[4 * 136]);
            }
#pragma unroll
            for (int mt = 0; mt < 2; mt++)
#pragma unroll
                for (int nt = 0; nt < 8; nt++)
                    mma_tf32(acc[mt][nt], af[mt], bf[nt]);
        }
        __syncthreads();
    }

    // epilogue: add bias, write C
#pragma unroll
    for (int mt = 0; mt < 2; mt++) {
        const int r0 = bm + wm + mt * 16 + gid;
#pragma unroll
        for (int nt = 0; nt < 8; nt++) {
            const int cc = bn + wn + nt * 8 + 2 * tig;
            float2 bb = *(const float2*)(bias + cc);
            float2 v0, v1;
            v0.x = acc[mt][nt][0] + bb.x; v0.y = acc[mt][nt][1] + bb.y;
            v1.x = acc[mt][nt][2] + bb.x; v1.y = acc[mt][nt][3] + bb.y;
            *(float2*)(C + (size_t)r0 * N + cc) = v0;
            *(float2*)(C + (size_t)(r0 + 8) * N + cc) = v1;
        }
    }
}

// ---------------------------------------------------------------------------
// Flash attention (causal) with tf32 mma. 64 q-rows x 64-key tiles, hd=64,
// 256 threads (8 warps). Warp w: m-band (w&3)*16, n-half (w>>2)*32.
// Q fragments hoisted to registers; its smem slot is reused for S/P.
// ---------------------------------------------------------------------------
static const int KP = 68;  // K / S pad: conflict-free fragment loads
static const int VP = 72;  // V pad: conflict-free B-fragment loads
static const int ATTN_SMEM = (64 * KP + 64 * VP + 64 * KP + 128) * 4;  // 53760 B

__global__ __launch_bounds__(256, 2) void attn_tf32_kernel(
    const float* __restrict__ Q, const float* __restrict__ KV,
    float* __restrict__ ctx)
{
    extern __shared__ float sm[];
    float* sK = sm;                       // [64][68]
    float* sV = sm + 64 * KP;             // [64][72]
    float* sS = sm + 64 * KP + 64 * VP;   // [64][68]  (Q staging, then S/P)
    float* sAlpha = sS + 64 * KP;         // [64]
    float* sL     = sAlpha + 64;          // [64]

    const int qb   = gridDim.x - 1 - blockIdx.x;  // big tiles scheduled first
    const int b    = blockIdx.y >> 4;
    const int h    = blockIdx.y & 15;
    const int tid  = threadIdx.x;
    const int lane = tid & 31;
    const int warp = tid >> 5;
    const int gid  = lane >> 2;
    const int tig  = lane & 3;
    const int mb   = (warp & 3) * 16;     // m band (q rows)
    const int wn   = (warp >> 2) * 32;    // n half (keys for S, d for O)

    const float* Qb = Q  + ((size_t)b * SEQ + (size_t)qb * 64) * DIM + h * HDIM;
    const float* Kb = KV + (size_t)b * SEQ * KVLD + h * HDIM;

    // stage Q into sS, extract fragments to registers
#pragma unroll
    for (int i = 0; i < 4; i++) {
        int idx = tid + (i << 8);
        int r = idx >> 4, c = (idx & 15) << 2;
        *(float4*)&sS[r * KP + c] = *(const float4*)(Qb + (size_t)r * DIM + c);
    }
    __syncthreads();

    unsigned qf[8][4];
#pragma unroll
    for (int ks = 0; ks < 8; ks++) {
        const float* p = sS + (mb + gid) * KP + ks * 8 + tig;
        qf[ks][0] = f2tf(p[0]);
        qf[ks][1] = f2tf(p[8 * KP]);
        qf[ks][2] = f2tf(p[4]);
        qf[ks][3] = f2tf(p[8 * KP + 4]);
    }

    // softmax owner mapping: thread t handles row t>>2, 16-col segment (t&3)*16
    const int srow = tid >> 2;
    const int sseg = (tid & 3) * 16;
    float m_s = -INFINITY, l_s = 0.f;

    float Oacc[4][4] = {};
    const float sc = 0.125f;  // 1/sqrt(64)

    for (int j = 0; j <= qb; ++j) {
        __syncthreads();  // protect sK/sV/sS reads of previous iteration
        // load K/V tile j
#pragma unroll
        for (int i = 0; i < 4; i++) {
            int idx = tid + (i << 8);
            int r = idx >> 4, c = (idx & 15) << 2;
            const float* kp = Kb + (size_t)(j * 64 + r) * KVLD + c;
            *(float4*)&sK[r * KP + c] = *(const float4*)kp;
            *(float4*)&sV[r * VP + c] = *(const float4*)(kp + DIM);
        }
        __syncthreads();

        // S = Q @ K^T  (k = d, 8 steps)
        float sacc[4][4] = {};
#pragma unroll
        for (int ks = 0; ks < 8; ks++) {
            unsigned bf[4][2];
#pragma unroll
            for (int nt = 0; nt < 4; nt++) {
                const float* p = sK + (wn + nt * 8 + gid) * KP + ks * 8 + tig;
                bf[nt][0] = f2tf(p[0]);
                bf[nt][1] = f2tf(p[4]);
            }
#pragma unroll
            for (int nt = 0; nt < 4; nt++)
                mma_tf32(sacc[nt], qf[ks], bf[nt]);
        }

        // write S (scaled + causal-masked on diagonal tile) into sS
        const int r0 = mb + gid;
        if (j == qb) {
#pragma unroll
            for (int nt = 0; nt < 4; nt++) {
                const int col = wn + nt * 8 + 2 * tig;
                sS[r0 * KP + col]           = (col     <= r0    ) ? sacc[nt][0] * sc : -1e30f;
                sS[r0 * KP + col + 1]       = (col + 1 <= r0    ) ? sacc[nt][1] * sc : -1e30f;
                sS[(r0 + 8) * KP + col]     = (col     <= r0 + 8) ? sacc[nt][2] * sc : -1e30f;
                sS[(r0 + 8) * KP + col + 1] = (col + 1 <= r0 + 8) ? sacc[nt][3] * sc : -1e30f;
            }
        } else {
#pragma unroll
            for (int nt = 0; nt < 4; nt++) {
                const int col = wn + nt * 8 + 2 * tig;
                float2 v0, v1;
                v0.x = sacc[nt][0] * sc; v0.y = sacc[nt][1] * sc;
                v1.x = sacc[nt][2] * sc; v1.y = sacc[nt][3] * sc;
                *(float2*)&sS[r0 * KP + col]       = v0;
                *(float2*)&sS[(r0 + 8) * KP + col] = v1;
            }
        }
        __syncthreads();

        // online softmax on sS (in place -> P), row state in registers
        {
            float4 v[4];
#pragma unroll
            for (int ii = 0; ii < 4; ii++)
                v[ii] = *(float4*)&sS[srow * KP + sseg + ii * 4];
            float mx = -INFINITY;
#pragma unroll
            for (int ii = 0; ii < 4; ii++)
                mx = fmaxf(mx, fmaxf(fmaxf(v[ii].x, v[ii].y), fmaxf(v[ii].z, v[ii].w)));
            mx = fmaxf(mx, __shfl_xor_sync(0xffffffffu, mx, 1));
            mx = fmaxf(mx, __shfl_xor_sync(0xffffffffu, mx, 2));
            float mnew  = fmaxf(m_s, mx);
            float alpha = __expf(m_s - mnew);
            m_s = mnew;
            float rs = 0.f;
#pragma unroll
            for (int ii = 0; ii < 4; ii++) {
                v[ii].x = __expf(v[ii].x - mnew);
                v[ii].y = __expf(v[ii].y - mnew);
                v[ii].z = __expf(v[ii].z - mnew);
                v[ii].w = __expf(v[ii].w - mnew);
                rs += v[ii].x + v[ii].y + v[ii].z + v[ii].w;
                *(float4*)&sS[srow * KP + sseg + ii * 4] = v[ii];
            }
            rs += __shfl_xor_sync(0xffffffffu, rs, 1);
            rs += __shfl_xor_sync(0xffffffffu, rs, 2);
            l_s = l_s * alpha + rs;
            if ((tid & 3) == 0) sAlpha[srow] = alpha;
        }
        __syncthreads();

        // rescale O by alpha, then O += P @ V
        {
            const float a0 = sAlpha[mb + gid];
            const float a1 = sAlpha[mb + gid + 8];
#pragma unroll
            for (int nt = 0; nt < 4; nt++) {
                Oacc[nt][0] *= a0; Oacc[nt][1] *= a0;
                Oacc[nt][2] *= a1; Oacc[nt][3] *= a1;
            }
        }
#pragma unroll
        for (int ks = 0; ks < 8; ks++) {
            unsigned pf[4];
            const float* pp = sS + (mb + gid) * KP + ks * 8 + tig;
            pf[0] = f2tf(pp[0]);
            pf[1] = f2tf(pp[8 * KP]);
            pf[2] = f2tf(pp[4]);
            pf[3] = f2tf(pp[8 * KP + 4]);
            unsigned bf[4][2];
#pragma unroll
            for (int nt = 0; nt < 4; nt++) {
                const float* vp = sV + (ks * 8 + tig) * VP + wn + nt * 8 + gid;
                bf[nt][0] = f2tf(vp[0]);
                bf[nt][1] = f2tf(vp[4 * VP]);
            }
#pragma unroll
            for (int nt = 0; nt < 4; nt++)
                mma_tf32(Oacc[nt], pf, bf[nt]);
        }
    }

    // broadcast l, normalize, write ctx
    if ((tid & 3) == 0) sL[srow] = l_s;
    __syncthreads();
    const float inv0 = 1.0f / sL[mb + gid];
    const float inv1 = 1.0f / sL[mb + gid + 8];
    float* cb = ctx + ((size_t)b * SEQ + (size_t)qb * 64) * DIM + h * HDIM;
    const int r0 = mb + gid;
#pragma unroll
    for (int nt = 0; nt < 4; nt++) {
        const int col = wn + nt * 8 + 2 * tig;
        float2 o0, o1;
        o0.x = Oacc[nt][0] * inv0; o0.y = Oacc[nt][1] * inv0;
        o1.x = Oacc[nt][2] * inv1; o1.y = Oacc[nt][3] * inv1;
        *(float2*)(cb + (size_t)r0 * DIM + col)       = o0;
        *(float2*)(cb + (size_t)(r0 + 8) * DIM + col) = o1;
    }
}

// ---------------------------------------------------------------------------
extern "C" void kernel_launch(void* const* d_in, const int* in_sizes, int n_in,
                              void* d_out, int out_size)
{
    const float* x      = (const float*)d_in[0];
    // d_in[1] = mask (tril) — causality handled analytically
    const float* w_kvc  = (const float*)d_in[2];
    const float* b_kvc  = (const float*)d_in[3];
    const float* w_kvu  = (const float*)d_in[4];
    const float* b_kvu  = (const float*)d_in[5];
    const float* w_qc   = (const float*)d_in[6];
    const float* b_qc   = (const float*)d_in[7];
    const float* w_qu   = (const float*)d_in[8];
    const float* b_qu   = (const float*)d_in[9];
    const float* w_o    = (const float*)d_in[10];
    const float* b_o    = (const float*)d_in[11];
    float* out = (float*)d_out;

    float *kvlat, *kvup, *qlat, *q, *ctx;
    cudaGetSymbolAddress((void**)&kvlat, g_kvlat);
    cudaGetSymbolAddress((void**)&kvup,  g_kvup);
    cudaGetSymbolAddress((void**)&qlat,  g_qlat);
    cudaGetSymbolAddress((void**)&q,     g_q);
    cudaGetSymbolAddress((void**)&ctx,   g_ctx);

    cudaFuncSetAttribute(gemm_tf32_kernel, cudaFuncAttributeMaxDynamicSharedMemorySize, GEMM_SMEM);
    cudaFuncSetAttribute(attn_tf32_kernel, cudaFuncAttributeMaxDynamicSharedMemorySize, ATTN_SMEM);

    dim3 t(256);

    // kv_latent = x @ w_kvc + b_kvc                [8192,128]
    gemm_tf32_kernel<<<dim3(LATENT / 128, MTOT / 128), t, GEMM_SMEM>>>(x, w_kvc, b_kvc, kvlat, MTOT, LATENT, DIM);
    // kv_up = kv_latent @ w_kvu + b_kvu            [8192,2048] = K|V
    gemm_tf32_kernel<<<dim3(2 * DIM / 128, MTOT / 128), t, GEMM_SMEM>>>(kvlat, w_kvu, b_kvu, kvup, MTOT, 2 * DIM, LATENT);
    // q_latent = x @ w_qc + b_qc                   [8192,256]
    gemm_tf32_kernel<<<dim3(QRANK / 128, MTOT / 128), t, GEMM_SMEM>>>(x, w_qc, b_qc, qlat, MTOT, QRANK, DIM);
    // Q = q_latent @ w_qu + b_qu                   [8192,1024]
    gemm_tf32_kernel<<<dim3(DIM / 128, MTOT / 128), t, GEMM_SMEM>>>(qlat, w_qu, b_qu, q, MTOT, DIM, QRANK);

    // attention -> ctx
    attn_tf32_kernel<<<dim3(SEQ / 64, BATCH * NHEAD), t, ATTN_SMEM>>>(q, kvup, ctx);

    // out = ctx @ w_o + b_o                        [8192,1024]
    gemm_tf32_kernel<<<dim3(DIM / 128, MTOT / 128), t, GEMM_SMEM>>>(ctx, w_o, b_o, out, MTOT, DIM, DIM);
}

// round 5
// speedup vs baseline: 6.5030x; 1.0708x over previous
#include <cuda_runtime.h>
#include <math.h>

// Problem constants
static const int BATCH  = 4;
static const int SEQ    = 2048;
static const int DIM    = 1024;
static const int NHEAD  = 16;
static const int HDIM   = 64;
static const int LATENT = 128;
static const int QRANK  = 256;
static const int MTOT   = BATCH * SEQ;          // 8192
static const int KVLD   = 2 * DIM;              // 2048

// Scratch (no allocations allowed) ------------------------------------------
__device__ float g_kvlat[(size_t)MTOT * LATENT];
__device__ float g_kvup [(size_t)MTOT * 2 * DIM];
__device__ float g_qlat [(size_t)MTOT * QRANK];
__device__ float g_q    [(size_t)MTOT * DIM];
__device__ float g_ctx  [(size_t)MTOT * DIM];

// ---------------------------------------------------------------------------
// tf32 helpers
// ---------------------------------------------------------------------------
__device__ __forceinline__ unsigned f2tf(float x) {
    unsigned u;
    asm("cvt.rna.tf32.f32 %0, %1;" : "=r"(u) : "f"(x));
    return u;
}

__device__ __forceinline__ void mma_tf32(float* d, const unsigned* a, const unsigned* b) {
    asm volatile(
        "mma.sync.aligned.m16n8k8.row.col.f32.tf32.tf32.f32 "
        "{%0,%1,%2,%3}, {%4,%5,%6,%7}, {%8,%9}, {%0,%1,%2,%3};"
        : "+f"(d[0]), "+f"(d[1]), "+f"(d[2]), "+f"(d[3])
        : "r"(a[0]), "r"(a[1]), "r"(a[2]), "r"(a[3]), "r"(b[0]), "r"(b[1]));
}

__device__ __forceinline__ void cpa16(float* smem, const float* g) {
    unsigned s = (unsigned)__cvta_generic_to_shared(smem);
    asm volatile("cp.async.cg.shared.global [%0], [%1], 16;" :: "r"(s), "l"(g));
}
__device__ __forceinline__ void cp_commit() { asm volatile("cp.async.commit_group;"); }
__device__ __forceinline__ void cp_wait1()  { asm volatile("cp.async.wait_group 1;"); }
__device__ __forceinline__ void cp_wait0()  { asm volatile("cp.async.wait_group 0;"); }

// ---------------------------------------------------------------------------
// tf32 GEMM: C[M,N] = A[M,K] @ W[K,N] + bias. BM=BN=128, BK=32, 256 threads.
// ---------------------------------------------------------------------------
static const int GA_STRIDE = 128 * 36;
static const int GW_STRIDE = 32 * 136;
static const int GEMM_SMEM = (2 * GA_STRIDE + 2 * GW_STRIDE) * 4;  // 71680 B

__global__ __launch_bounds__(256, 2) void gemm_tf32_kernel(
    const float* __restrict__ A, const float* __restrict__ W,
    const float* __restrict__ bias, float* __restrict__ C,
    int M, int N, int K)
{
    extern __shared__ float sm[];
    float* sA = sm;                   // [2][128][36]
    float* sW = sm + 2 * GA_STRIDE;   // [2][32][136]

    const int tid  = threadIdx.x;
    const int lane = tid & 31;
    const int warp = tid >> 5;
    const int gid  = lane >> 2;
    const int tig  = lane & 3;
    const int bm   = blockIdx.y * 128;
    const int bn   = blockIdx.x * 128;
    const int wm   = (warp & 3) * 32;
    const int wn   = (warp >> 2) * 64;

    const int a_r = tid >> 3;
    const int a_c = (tid & 7) * 4;
    const int w_r = tid >> 5;
    const int w_c = (tid & 31) * 4;

    const float* Ag = A + (size_t)(bm + a_r) * K + a_c;
    const float* Wg = W + (size_t)w_r * N + bn + w_c;

    float acc[2][8][4] = {};
    const int NC = K / 32;

    {
#pragma unroll
        for (int i = 0; i < 4; i++)
            cpa16(sA + (a_r + i * 32) * 36 + a_c, Ag + (size_t)i * 32 * K);
#pragma unroll
        for (int i = 0; i < 4; i++)
            cpa16(sW + (w_r + i * 8) * 136 + w_c, Wg + (size_t)i * 8 * N);
        cp_commit();
    }

    for (int c = 0; c < NC; ++c) {
        const int buf = c & 1;
        if (c + 1 < NC) {
            float* dA = sA + (buf ^ 1) * GA_STRIDE;
            float* dW = sW + (buf ^ 1) * GW_STRIDE;
            const float* Agc = Ag + (c + 1) * 32;
            const float* Wgc = Wg + (size_t)(c + 1) * 32 * N;
#pragma unroll
            for (int i = 0; i < 4; i++)
                cpa16(dA + (a_r + i * 32) * 36 + a_c, Agc + (size_t)i * 32 * K);
#pragma unroll
            for (int i = 0; i < 4; i++)
                cpa16(dW + (w_r + i * 8) * 136 + w_c, Wgc + (size_t)i * 8 * N);
            cp_commit();
            cp_wait1();
        } else {
            cp_wait0();
        }
        __syncthreads();

        const float* ab = sA + buf * GA_STRIDE;
        const float* wb = sW + buf * GW_STRIDE;
#pragma unroll
        for (int ks = 0; ks < 4; ks++) {
            unsigned af[2][4];
#pragma unroll
            for (int mt = 0; mt < 2; mt++) {
                const float* p = ab + (wm + mt * 16 + gid) * 36 + ks * 8 + tig;
                af[mt][0] = f2tf(p[0]);
                af[mt][1] = f2tf(p[8 * 36]);
                af[mt][2] = f2tf(p[4]);
                af[mt][3] = f2tf(p[8 * 36 + 4]);
            }
            unsigned bf[8][2];
#pragma unroll
            for (int nt = 0; nt < 8; nt++) {
                const float* p = wb + (ks * 8 + tig) * 136 + wn + nt * 8 + gid;
                bf[nt][0] = f2tf(p[0]);
                bf[nt][1] = f2tf(p[4 * 136]);
            }
#pragma unroll
            for (int mt = 0; mt < 2; mt++)
#pragma unroll
                for (int nt = 0; nt < 8; nt++)
                    mma_tf32(acc[mt][nt], af[mt], bf[nt]);
        }
        __syncthreads();
    }

#pragma unroll
    for (int mt = 0; mt < 2; mt++) {
        const int r0 = bm + wm + mt * 16 + gid;
#pragma unroll
        for (int nt = 0; nt < 8; nt++) {
            const int cc = bn + wn + nt * 8 + 2 * tig;
            float2 bb = *(const float2*)(bias + cc);
            float2 v0, v1;
            v0.x = acc[mt][nt][0] + bb.x; v0.y = acc[mt][nt][1] + bb.y;
            v1.x = acc[mt][nt][2] + bb.x; v1.y = acc[mt][nt][3] + bb.y;
            *(float2*)(C + (size_t)r0 * N + cc) = v0;
            *(float2*)(C + (size_t)(r0 + 8) * N + cc) = v1;
        }
    }
}

// ---------------------------------------------------------------------------
// Flash attention v2 (causal, tf32 mma): 128 q-rows per block, warp owns 16
// rows -> warp-local softmax (quad shuffles only). cp.async double-buffered
// K/V (one __syncthreads per tile). Per-warp private P slice in smem.
// ---------------------------------------------------------------------------
static const int KP2 = 68;
static const int VP2 = 72;
static const int PP2 = 68;
static const int AK_STRIDE = 64 * KP2;
static const int AV_STRIDE = 64 * VP2;
static const int ATTN_SMEM = (2 * AK_STRIDE + 2 * AV_STRIDE + 8 * 16 * PP2) * 4; // 106496 B

__global__ __launch_bounds__(256, 2) void attn_tf32_kernel(
    const float* __restrict__ Q, const float* __restrict__ KV,
    float* __restrict__ ctx)
{
    extern __shared__ float sm[];
    float* sK = sm;                                   // [2][64][KP2]
    float* sV = sm + 2 * AK_STRIDE;                   // [2][64][VP2]
    float* sP = sm + 2 * AK_STRIDE + 2 * AV_STRIDE;   // [8][16][PP2]

    const int qb   = gridDim.x - 1 - blockIdx.x;  // big tiles first
    const int b    = blockIdx.y >> 4;
    const int h    = blockIdx.y & 15;
    const int tid  = threadIdx.x;
    const int lane = tid & 31;
    const int warp = tid >> 5;
    const int gid  = lane >> 2;
    const int tig  = lane & 3;
    const int mb   = warp * 16;           // warp's 16 q rows within block
    float* sPw = sP + warp * 16 * PP2;    // warp-private P slice

    const float* Qb = Q  + ((size_t)b * SEQ + (size_t)qb * 128) * DIM + h * HDIM;
    const float* Kb = KV + (size_t)b * SEQ * KVLD + h * HDIM;

    // prologue: prefetch K/V tile 0
    {
#pragma unroll
        for (int i = 0; i < 4; i++) {
            int idx = tid + (i << 8);
            int r = idx >> 4, c = (idx & 15) << 2;
            const float* src = Kb + (size_t)r * KVLD + c;
            cpa16(sK + r * KP2 + c, src);
            cpa16(sV + r * VP2 + c, src + DIM);
        }
        cp_commit();
    }

    // stage this warp's Q rows into its P slice, extract fragments
#pragma unroll
    for (int i = 0; i < 8; i++) {
        int idx = lane + (i << 5);
        int r = idx >> 4, c = (idx & 15) << 2;
        *(float4*)&sPw[r * PP2 + c] = *(const float4*)(Qb + (size_t)(mb + r) * DIM + c);
    }
    __syncwarp();
    unsigned qf[8][4];
#pragma unroll
    for (int ks = 0; ks < 8; ks++) {
        const float* p = sPw + gid * PP2 + ks * 8 + tig;
        qf[ks][0] = f2tf(p[0]);
        qf[ks][1] = f2tf(p[8 * PP2]);
        qf[ks][2] = f2tf(p[4]);
        qf[ks][3] = f2tf(p[8 * PP2 + 4]);
    }
    __syncwarp();

    float ms0 = -INFINITY, ms1 = -INFINITY, ls0 = 0.f, ls1 = 0.f;
    float Oacc[8][4] = {};
    const int jmax = 2 * qb + 1;
    const int rg0  = qb * 128 + mb + gid;   // row of accumulator vals {0,1}; +8 for {2,3}
    const float sc = 0.125f;                // 1/sqrt(64)

    for (int j = 0; j <= jmax; ++j) {
        const int buf = j & 1;
        cp_wait0();
        __syncthreads();   // tile j visible to all; all done reading buf^1

        if (j < jmax) {
            float* dK = sK + (buf ^ 1) * AK_STRIDE;
            float* dV = sV + (buf ^ 1) * AV_STRIDE;
            const float* src0 = Kb + (size_t)(j + 1) * 64 * KVLD;
#pragma unroll
            for (int i = 0; i < 4; i++) {
                int idx = tid + (i << 8);
                int r = idx >> 4, c = (idx & 15) << 2;
                const float* src = src0 + (size_t)r * KVLD + c;
                cpa16(dK + r * KP2 + c, src);
                cpa16(dV + r * VP2 + c, src + DIM);
            }
            cp_commit();
        }

        const float* kb = sK + buf * AK_STRIDE;
        const float* vb = sV + buf * AV_STRIDE;

        // S = Q @ K^T  (warp: 16 rows x 64 keys)
        float sacc[8][4] = {};
#pragma unroll
        for (int ks = 0; ks < 8; ks++) {
#pragma unroll
            for (int nt = 0; nt < 8; nt++) {
                unsigned bf[2];
                const float* p = kb + (nt * 8 + gid) * KP2 + ks * 8 + tig;
                bf[0] = f2tf(p[0]);
                bf[1] = f2tf(p[4]);
                mma_tf32(sacc[nt], qf[ks], bf);
            }
        }

        // scale + causal mask (diagonal tiles only)
        if (j * 64 + 63 > qb * 128 + mb) {
#pragma unroll
            for (int nt = 0; nt < 8; nt++) {
                const int cg = j * 64 + nt * 8 + 2 * tig;
                sacc[nt][0] = (cg     <= rg0    ) ? sacc[nt][0] * sc : -1e30f;
                sacc[nt][1] = (cg + 1 <= rg0    ) ? sacc[nt][1] * sc : -1e30f;
                sacc[nt][2] = (cg     <= rg0 + 8) ? sacc[nt][2] * sc : -1e30f;
                sacc[nt][3] = (cg + 1 <= rg0 + 8) ? sacc[nt][3] * sc : -1e30f;
            }
        } else {
#pragma unroll
            for (int nt = 0; nt < 8; nt++) {
                sacc[nt][0] *= sc; sacc[nt][1] *= sc;
                sacc[nt][2] *= sc; sacc[nt][3] *= sc;
            }
        }

        // warp-local online softmax (rows rg0 and rg0+8)
        float m0 = -INFINITY, m1 = -INFINITY;
#pragma unroll
        for (int nt = 0; nt < 8; nt++) {
            m0 = fmaxf(m0, fmaxf(sacc[nt][0], sacc[nt][1]));
            m1 = fmaxf(m1, fmaxf(sacc[nt][2], sacc[nt][3]));
        }
        m0 = fmaxf(m0, __shfl_xor_sync(0xffffffffu, m0, 1));
        m0 = fmaxf(m0, __shfl_xor_sync(0xffffffffu, m0, 2));
        m1 = fmaxf(m1, __shfl_xor_sync(0xffffffffu, m1, 1));
        m1 = fmaxf(m1, __shfl_xor_sync(0xffffffffu, m1, 2));
        const float mn0 = fmaxf(ms0, m0);
        const float mn1 = fmaxf(ms1, m1);
        const float a0  = __expf(ms0 - mn0);
        const float a1  = __expf(ms1 - mn1);
        ms0 = mn0; ms1 = mn1;
        float rs0 = 0.f, rs1 = 0.f;
#pragma unroll
        for (int nt = 0; nt < 8; nt++) {
            sacc[nt][0] = __expf(sacc[nt][0] - mn0);
            sacc[nt][1] = __expf(sacc[nt][1] - mn0);
            sacc[nt][2] = __expf(sacc[nt][2] - mn1);
            sacc[nt][3] = __expf(sacc[nt][3] - mn1);
            rs0 += sacc[nt][0] + sacc[nt][1];
            rs1 += sacc[nt][2] + sacc[nt][3];
        }
        rs0 += __shfl_xor_sync(0xffffffffu, rs0, 1);
        rs0 += __shfl_xor_sync(0xffffffffu, rs0, 2);
        rs1 += __shfl_xor_sync(0xffffffffu, rs1, 1);
        rs1 += __shfl_xor_sync(0xffffffffu, rs1, 2);
        ls0 = ls0 * a0 + rs0;
        ls1 = ls1 * a1 + rs1;
#pragma unroll
        for (int nt = 0; nt < 8; nt++) {
            Oacc[nt][0] *= a0; Oacc[nt][1] *= a0;
            Oacc[nt][2] *= a1; Oacc[nt][3] *= a1;
        }

        // P -> warp-private smem (accumulator layout), reload as A fragments
        __syncwarp();
#pragma unroll
        for (int nt = 0; nt < 8; nt++) {
            float2 p0, p1;
            p0.x = sacc[nt][0]; p0.y = sacc[nt][1];
            p1.x = sacc[nt][2]; p1.y = sacc[nt][3];
            *(float2*)&sPw[gid * PP2 + nt * 8 + 2 * tig]       = p0;
            *(float2*)&sPw[(gid + 8) * PP2 + nt * 8 + 2 * tig] = p1;
        }
        __syncwarp();

        // O += P @ V
#pragma unroll
        for (int ks = 0; ks < 8; ks++) {
            unsigned pf[4];
            const float* pp = sPw + gid * PP2 + ks * 8 + tig;
            pf[0] = f2tf(pp[0]);
            pf[1] = f2tf(pp[8 * PP2]);
            pf[2] = f2tf(pp[4]);
            pf[3] = f2tf(pp[8 * PP2 + 4]);
#pragma unroll
            for (int nt = 0; nt < 8; nt++) {
                unsigned bf[2];
                const float* vp = vb + (ks * 8 + tig) * VP2 + nt * 8 + gid;
                bf[0] = f2tf(vp[0]);
                bf[1] = f2tf(vp[4 * VP2]);
                mma_tf32(Oacc[nt], pf, bf);
            }
        }
    }

    // epilogue: normalize + write ctx
    const float inv0 = 1.0f / ls0;
    const float inv1 = 1.0f / ls1;
    float* cb = ctx + ((size_t)b * SEQ + (size_t)qb * 128 + mb) * DIM + h * HDIM;
#pragma unroll
    for (int nt = 0; nt < 8; nt++) {
        const int col = nt * 8 + 2 * tig;
        float2 o0, o1;
        o0.x = Oacc[nt][0] * inv0; o0.y = Oacc[nt][1] * inv0;
        o1.x = Oacc[nt][2] * inv1; o1.y = Oacc[nt][3] * inv1;
        *(float2*)(cb + (size_t)gid * DIM + col)       = o0;
        *(float2*)(cb + (size_t)(gid + 8) * DIM + col) = o1;
    }
}

// ---------------------------------------------------------------------------
extern "C" void kernel_launch(void* const* d_in, const int* in_sizes, int n_in,
                              void* d_out, int out_size)
{
    const float* x      = (const float*)d_in[0];
    // d_in[1] = mask (tril) — causality handled analytically
    const float* w_kvc  = (const float*)d_in[2];
    const float* b_kvc  = (const float*)d_in[3];
    const float* w_kvu  = (const float*)d_in[4];
    const float* b_kvu  = (const float*)d_in[5];
    const float* w_qc   = (const float*)d_in[6];
    const float* b_qc   = (const float*)d_in[7];
    const float* w_qu   = (const float*)d_in[8];
    const float* b_qu   = (const float*)d_in[9];
    const float* w_o    = (const float*)d_in[10];
    const float* b_o    = (const float*)d_in[11];
    float* out = (float*)d_out;

    float *kvlat, *kvup, *qlat, *q, *ctx;
    cudaGetSymbolAddress((void**)&kvlat, g_kvlat);
    cudaGetSymbolAddress((void**)&kvup,  g_kvup);
    cudaGetSymbolAddress((void**)&qlat,  g_qlat);
    cudaGetSymbolAddress((void**)&q,     g_q);
    cudaGetSymbolAddress((void**)&ctx,   g_ctx);

    cudaFuncSetAttribute(gemm_tf32_kernel, cudaFuncAttributeMaxDynamicSharedMemorySize, GEMM_SMEM);
    cudaFuncSetAttribute(attn_tf32_kernel, cudaFuncAttributeMaxDynamicSharedMemorySize, ATTN_SMEM);

    dim3 t(256);

    // kv_latent = x @ w_kvc + b_kvc                [8192,128]
    gemm_tf32_kernel<<<dim3(LATENT / 128, MTOT / 128), t, GEMM_SMEM>>>(x, w_kvc, b_kvc, kvlat, MTOT, LATENT, DIM);
    // kv_up = kv_latent @ w_kvu + b_kvu            [8192,2048] = K|V
    gemm_tf32_kernel<<<dim3(2 * DIM / 128, MTOT / 128), t, GEMM_SMEM>>>(kvlat, w_kvu, b_kvu, kvup, MTOT, 2 * DIM, LATENT);
    // q_latent = x @ w_qc + b_qc                   [8192,256]
    gemm_tf32_kernel<<<dim3(QRANK / 128, MTOT / 128), t, GEMM_SMEM>>>(x, w_qc, b_qc, qlat, MTOT, QRANK, DIM);
    // Q = q_latent @ w_qu + b_qu                   [8192,1024]
    gemm_tf32_kernel<<<dim3(DIM / 128, MTOT / 128), t, GEMM_SMEM>>>(qlat, w_qu, b_qu, q, MTOT, DIM, QRANK);

    // attention -> ctx   (128 q rows per block)
    attn_tf32_kernel<<<dim3(SEQ / 128, BATCH * NHEAD), t, ATTN_SMEM>>>(q, kvup, ctx);

    // out = ctx @ w_o + b_o                        [8192,1024]
    gemm_tf32_kernel<<<dim3(DIM / 128, MTOT / 128), t, GEMM_SMEM>>>(ctx, w_o, b_o, out, MTOT, DIM, DIM);
}